// round 15
// baseline (speedup 1.0000x reference)
#include <cuda_runtime.h>
#include <cuda_bf16.h>
#include <cstdint>

#define B_  32
#define CT  512
#define GC  128
#define H_  56
#define W_  56
#define HW  3136
#define FEATS_BASE (B_*GC*HW)   // 12,845,056 floats: mem section size

// Scratch (device-global; allocation inside kernel_launch is forbidden)
__device__ float g_q[B_*GC*HW];                 // q post elu+1, channel-major [b][c][n]
__device__ float g_kv[B_*4*32*32];              // kv accumulators per (b,h,d,e)
__device__ float g_ksum[B_*4*32];               // k column sums per (b,h,d)
__device__ __nv_bfloat16 g_xt[(long)B_*HW*256]; // [b][px][ Xhi(128) | Xlo(128) ] bf16
__device__ __nv_bfloat16 g_wh[256*128];         // W hi bf16, [o][k]
__device__ __nv_bfloat16 g_wl[256*128];         // W lo bf16, [o][k]

__device__ __forceinline__ uint32_t smem_to_u32(const void* p) {
    uint32_t a;
    asm("{ .reg .u64 t; cvta.to.shared.u64 t, %1; cvt.u32.u64 %0, t; }" : "=r"(a) : "l"(p));
    return a;
}

#define LDMATRIX_X4(r0, r1, r2, r3, addr) \
    asm volatile("ldmatrix.sync.aligned.m8n8.x4.shared.b16 {%0,%1,%2,%3}, [%4];" \
                 : "=r"(r0), "=r"(r1), "=r"(r2), "=r"(r3) : "r"(addr))

#define MMA_16816(c0, c1, c2, c3, a0, a1, a2, a3, b0, b1) \
    asm volatile("mma.sync.aligned.m16n8k16.row.col.f32.bf16.bf16.f32 " \
                 "{%0,%1,%2,%3}, {%4,%5,%6,%7}, {%8,%9}, {%0,%1,%2,%3};" \
                 : "+f"(c0), "+f"(c1), "+f"(c2), "+f"(c3) \
                 : "r"(a0), "r"(a1), "r"(a2), "r"(a3), "r"(b0), "r"(b1))

__device__ __forceinline__ void cp_async4(uint32_t dst, const void* src, bool valid) {
    int sz = valid ? 4 : 0;
    asm volatile("cp.async.ca.shared.global [%0], [%1], 4, %2;"
                 :: "r"(dst), "l"(src), "r"(sz));
}
#define CP_COMMIT() asm volatile("cp.async.commit_group;" ::: "memory")
#define CP_WAIT(n)  asm volatile("cp.async.wait_group %0;" :: "n"(n) : "memory")

// ---------------------------------------------------------------------------
__global__ __launch_bounds__(256) void prep_kernel(const float* __restrict__ wqk) {
    int i = blockIdx.x * 256 + threadIdx.x;
    if (i < 256 * 128) {
        float w = wqk[i];
        __nv_bfloat16 h = __float2bfloat16_rn(w);
        g_wh[i] = h;
        g_wl[i] = __float2bfloat16_rn(w - __bfloat162float(h));
    }
    if (i < B_*4*32*32) g_kv[i] = 0.f;
    if (i < B_*4*32)    g_ksum[i] = 0.f;
}

// ---------------------------------------------------------------------------
__global__ void copy_mem_kernel(const float4* __restrict__ x, float4* __restrict__ out) {
    long i = (long)blockIdx.x * blockDim.x + threadIdx.x;
    const long total = (long)B_ * GC * HW / 4;
    if (i >= total) return;
    const int per_b = GC * HW / 4;
    int b = (int)(i / per_b);
    int r = (int)(i % per_b);
    out[i] = x[(long)b * (CT * HW / 4) + r];
}

// ---------------------------------------------------------------------------
// Transpose + split-bf16 convert: x[b][128+c][px] -> g_xt[b][px][ hi(128) | lo(128) ]
__global__ __launch_bounds__(256) void cvt_kernel(const float* __restrict__ x) {
    __shared__ float tile[32][33];
    int b = blockIdx.z;
    int ch0 = blockIdx.y * 32;
    int px0 = blockIdx.x * 32;
    int tid = threadIdx.x;
    int tx = tid & 31, ty = tid >> 5;

    const float* src = x + ((long)b * CT + GC + ch0) * HW + px0;
    #pragma unroll
    for (int r = 0; r < 4; r++) {
        int c = ty + r * 8;
        tile[c][tx] = src[(long)c * HW + tx];
    }
    __syncthreads();

    uint32_t* dstu = reinterpret_cast<uint32_t*>(g_xt);
    #pragma unroll
    for (int r = 0; r < 4; r++) {
        int pxl = ty + r * 8;
        long rowBase = ((long)b * HW + px0 + pxl) * 128;
        int pi = (tx < 16) ? tx : (tx - 16);
        float f0 = tile[2*pi][pxl];
        float f1 = tile[2*pi+1][pxl];
        __nv_bfloat16 h0 = __float2bfloat16_rn(f0);
        __nv_bfloat16 h1 = __float2bfloat16_rn(f1);
        uint32_t val;
        if (tx < 16) {
            val = (uint32_t)__bfloat16_as_ushort(h0) | ((uint32_t)__bfloat16_as_ushort(h1) << 16);
            dstu[rowBase + (ch0 >> 1) + pi] = val;
        } else {
            __nv_bfloat16 l0 = __float2bfloat16_rn(f0 - __bfloat162float(h0));
            __nv_bfloat16 l1 = __float2bfloat16_rn(f1 - __bfloat162float(h1));
            val = (uint32_t)__bfloat16_as_ushort(l0) | ((uint32_t)__bfloat16_as_ushort(l1) << 16);
            dstu[rowBase + 64 + (ch0 >> 1) + pi] = val;
        }
    }
}

// ---------------------------------------------------------------------------
// qk GEMM via mma.sync split-bf16. Block: 128 o x 128 px, 8 warps (32o x 64n).
// q branch: store channel-major. k branch: fused kv/ksum; V chunk 0 via
// cp.async overlapping the MMA mainloop (DISJOINT smem region), chunks 1-3
// prefetched into registers under the reduce loop, single smem buffer.
#define BS_STRIDE 264
#define WC_STRIDE 24
#define SM_BS     0
#define SM_WC     (128 * BS_STRIDE * 2)      // 67584
#define WC_HALF   (128 * WC_STRIDE * 2)      // 6144
#define SM_VS     (SM_WC + 2 * WC_HALF)      // 79872 (after W chunk region!)
#define VS_STR    36
#define VS_BUF    (128 * VS_STR * 4)         // 18432
#define SM_TOTAL  (SM_VS + VS_BUF)           // 98304
#define DS_STR    132

__global__ __launch_bounds__(256, 2) void qk_mma_kernel(const float* __restrict__ x,
                                                        const float* __restrict__ bqk) {
    extern __shared__ __align__(16) char sm[];
    __nv_bfloat16* Bs = (__nv_bfloat16*)(sm + SM_BS);
    float* Ds = (float*)sm;                 // union over Bs; used after compute
    float* Vs = (float*)(sm + SM_VS);

    int b = blockIdx.z;
    int oBase = blockIdx.y * 128;
    int pBase = blockIdx.x * 128;
    int tid = threadIdx.x;
    int wid = tid >> 5, lane = tid & 31;
    int oSub = (wid & 3) * 32;
    int nSub = (wid >> 2) * 64;
    bool isK = (blockIdx.y == 1);

    uint32_t vsBase = smem_to_u32(Vs);
    int vc = tid >> 7;            // 0/1: channel parity
    int vp = tid & 127;           // px
    bool okv = (pBase + vp) < HW;

    // ---- prefetch V chunk 0 (head 0: channels [0,32)) into disjoint VS
    if (isK) {
        const float* Vb = x + ((long)b * CT + GC) * HW + pBase;
        #pragma unroll
        for (int it = 0; it < 16; it++) {
            int c = vc + it * 2;                 // 0..31
            cp_async4(vsBase + (uint32_t)(vp * VS_STR + c) * 4, Vb + (long)c * HW + vp, okv);
        }
        CP_COMMIT();
    }

    // ---- load B tile: 128 px rows x 256 bf16 (hi|lo), guarded
    {
        const uint4* src = (const uint4*)(g_xt + ((long)b * HW + pBase) * 256);
        const uint4 z4 = make_uint4(0u, 0u, 0u, 0u);
        #pragma unroll
        for (int it = 0; it < 16; it++) {
            int idx = tid + it * 256;
            int row = idx >> 5;
            int j = idx & 31;
            uint4 v = (pBase + row < HW) ? src[row * 32 + j] : z4;
            *(uint4*)(Bs + row * BS_STRIDE + j * 8) = v;
        }
    }

    float acc[2][8][4];
    #pragma unroll
    for (int mt = 0; mt < 2; mt++)
        #pragma unroll
        for (int nt = 0; nt < 8; nt++)
            #pragma unroll
            for (int c = 0; c < 4; c++) acc[mt][nt][c] = 0.f;

    int wrow = tid >> 1, wseg = tid & 1;
    const uint4* ghp = (const uint4*)(g_wh + (long)(oBase + wrow) * 128 + wseg * 8);
    const uint4* glp = (const uint4*)(g_wl + (long)(oBase + wrow) * 128 + wseg * 8);
    uint4* sh = (uint4*)(sm + SM_WC + wrow * (WC_STRIDE * 2) + wseg * 16);
    uint4* sl = (uint4*)(sm + SM_WC + WC_HALF + wrow * (WC_STRIDE * 2) + wseg * 16);

    uint32_t aOff = (uint32_t)((oSub + (lane & 15)) * (WC_STRIDE * 2) + (lane >> 4) * 16);
    uint32_t aAddrH = smem_to_u32(sm + SM_WC) + aOff;
    uint32_t aAddrL = aAddrH + WC_HALF;

    uint32_t g = (uint32_t)(lane >> 3);
    uint32_t bRow = (uint32_t)(nSub + ((g >> 1) << 3) + (lane & 7));
    uint32_t bAddr0 = smem_to_u32(Bs) + bRow * (BS_STRIDE * 2) + (g & 1) * 16;

    uint4 ph = ghp[0];
    uint4 pl = glp[0];

    #pragma unroll
    for (int ks = 0; ks < 8; ks++) {
        __syncthreads();
        *sh = ph;
        *sl = pl;
        __syncthreads();
        if (ks < 7) {
            ph = ghp[(ks + 1) * 2];
            pl = glp[(ks + 1) * 2];
        }

        uint32_t aH[2][4], aL[2][4];
        #pragma unroll
        for (int mt = 0; mt < 2; mt++) {
            LDMATRIX_X4(aH[mt][0], aH[mt][1], aH[mt][2], aH[mt][3],
                        aAddrH + (uint32_t)(mt * 16 * (WC_STRIDE * 2)));
            LDMATRIX_X4(aL[mt][0], aL[mt][1], aL[mt][2], aL[mt][3],
                        aAddrL + (uint32_t)(mt * 16 * (WC_STRIDE * 2)));
        }
        int kc = ks * 16;
        uint32_t bkbH = (uint32_t)(kc * 2);
        uint32_t bkbL = (uint32_t)((128 + kc) * 2);

        #pragma unroll
        for (int m = 0; m < 4; m++) {
            uint32_t bOff = bAddr0 + (uint32_t)(m * 16 * (BS_STRIDE * 2));
            uint32_t hF[4], lF[4];
            LDMATRIX_X4(hF[0], hF[1], hF[2], hF[3], bOff + bkbH);
            LDMATRIX_X4(lF[0], lF[1], lF[2], lF[3], bOff + bkbL);
            #pragma unroll
            for (int sub = 0; sub < 2; sub++) {
                int nt = m * 2 + sub;
                uint32_t bh0 = hF[sub * 2], bh1 = hF[sub * 2 + 1];
                uint32_t bl0 = lF[sub * 2], bl1 = lF[sub * 2 + 1];
                #pragma unroll
                for (int mt = 0; mt < 2; mt++) {
                    MMA_16816(acc[mt][nt][0], acc[mt][nt][1], acc[mt][nt][2], acc[mt][nt][3],
                              aH[mt][0], aH[mt][1], aH[mt][2], aH[mt][3], bh0, bh1);
                    MMA_16816(acc[mt][nt][0], acc[mt][nt][1], acc[mt][nt][2], acc[mt][nt][3],
                              aH[mt][0], aH[mt][1], aH[mt][2], aH[mt][3], bl0, bl1);
                    MMA_16816(acc[mt][nt][0], acc[mt][nt][1], acc[mt][nt][2], acc[mt][nt][3],
                              aL[mt][0], aL[mt][1], aL[mt][2], aL[mt][3], bh0, bh1);
                }
            }
        }
    }
    __syncthreads();   // done with Bs/Wc; alias as Ds

    if (!isK) {
        // ---- q epilogue: Ds[o][n] stride 132, channel-major coalesced store
        #pragma unroll
        for (int mt = 0; mt < 2; mt++) {
            #pragma unroll
            for (int half = 0; half < 2; half++) {
                int row = oSub + mt * 16 + (lane >> 2) + half * 8;
                float bias = bqk[row];
                #pragma unroll
                for (int nt = 0; nt < 8; nt++) {
                    int col = nSub + nt * 8 + (lane & 3) * 2;
                    float v0 = acc[mt][nt][half * 2 + 0] + bias;
                    float v1 = acc[mt][nt][half * 2 + 1] + bias;
                    Ds[row * DS_STR + col]     = (v0 > 0.f) ? (v0 + 1.f) : __expf(v0);
                    Ds[row * DS_STR + col + 1] = (v1 > 0.f) ? (v1 + 1.f) : __expf(v1);
                }
            }
        }
        __syncthreads();
        float* base = g_q + (long)b * GC * HW + pBase;
        #pragma unroll
        for (int it = 0; it < 16; it++) {
            int idx = tid + it * 256;
            int o = idx >> 5, c4 = idx & 31;
            if (pBase + c4 * 4 < HW) {
                float4 v = *(float4*)(Ds + o * DS_STR + c4 * 4);
                *(float4*)(base + (long)o * HW + c4 * 4) = v;
            }
        }
    } else {
        // ---- k epilogue: Ds[px][c] (zeroed for invalid px), then fused
        //      kv/ksum reduction; V chunks 1-3 register-prefetched.
        #pragma unroll
        for (int mt = 0; mt < 2; mt++) {
            #pragma unroll
            for (int half = 0; half < 2; half++) {
                int row = oSub + mt * 16 + (lane >> 2) + half * 8;
                float bias = bqk[GC + row];
                #pragma unroll
                for (int nt = 0; nt < 8; nt++) {
                    int col = nSub + nt * 8 + (lane & 3) * 2;
                    bool ok = (pBase + col) < HW;   // col,col+1 same validity
                    float v0 = acc[mt][nt][half * 2 + 0] + bias;
                    float v1 = acc[mt][nt][half * 2 + 1] + bias;
                    v0 = (v0 > 0.f) ? (v0 + 1.f) : __expf(v0);
                    v1 = (v1 > 0.f) ? (v1 + 1.f) : __expf(v1);
                    Ds[col * DS_STR + row]       = ok ? v0 : 0.f;
                    Ds[(col + 1) * DS_STR + row] = ok ? v1 : 0.f;
                }
            }
        }

        int d  = tid >> 3;              // 0..31
        int e0 = (tid & 7) * 4;         // 0,4,..,28
        bool doKs = (e0 == 0);
        float vreg[16];

        #pragma unroll
        for (int ch = 0; ch < 4; ch++) {
            if (ch < 3) {   // register-prefetch chunk ch+1 (head ch+1, 32 ch)
                const float* Vb = x + ((long)b * CT + GC + (ch + 1) * 32) * HW + pBase;
                #pragma unroll
                for (int it = 0; it < 16; it++) {
                    int c = vc + it * 2;
                    vreg[it] = okv ? Vb[(long)c * HW + vp] : 0.f;
                }
            }
            if (ch == 0) { CP_WAIT(0); }
            __syncthreads();            // VS ready + Ds ready (ch 0)

            const float* Dk = Ds + ch * 32 + d;
            const float* Vv = Vs + e0;
            float a0 = 0.f, a1 = 0.f, a2 = 0.f, a3 = 0.f;
            float kss = 0.f;
            #pragma unroll 8
            for (int p = 0; p < 128; p++) {
                float kd = Dk[p * DS_STR];
                float4 v4 = *(const float4*)(Vv + p * VS_STR);
                a0 += kd * v4.x; a1 += kd * v4.y;
                a2 += kd * v4.z; a3 += kd * v4.w;
                if (doKs) kss += kd;
            }
            float* kvdst = g_kv + (((long)(b * 4 + ch) * 32 + d) * 32 + e0);
            atomicAdd(kvdst + 0, a0);
            atomicAdd(kvdst + 1, a1);
            atomicAdd(kvdst + 2, a2);
            atomicAdd(kvdst + 3, a3);
            if (doKs) atomicAdd(g_ksum + (b * 4 + ch) * 32 + d, kss);
            __syncthreads();            // all readers done before overwrite
            if (ch < 3) {
                #pragma unroll
                for (int it = 0; it < 16; it++) {
                    int c = vc + it * 2;
                    Vs[vp * VS_STR + c] = vreg[it];
                }
            }
        }
    }
}

// ---------------------------------------------------------------------------
// att: q read channel-major (lane-coalesced over n).
__global__ __launch_bounds__(256) void att_kernel(float* __restrict__ out) {
    __shared__ float4 kvs4[1024];
    __shared__ float  kms[128];
    int b = blockIdx.y;
    int p0 = blockIdx.x * 128;
    int tid = threadIdx.x;
    const float invHW = 1.f / (float)HW;
    const float4* kvsrc = (const float4*)(g_kv + (long)b * 4096);
    for (int idx = tid; idx < 1024; idx += 256) {
        float4 v = kvsrc[idx];
        v.x *= invHW; v.y *= invHW; v.z *= invHW; v.w *= invHW;
        kvs4[idx] = v;
    }
    if (tid < 128) kms[tid] = g_ksum[b * 128 + tid] * invHW;
    __syncthreads();

    int h = tid >> 6, lp = tid & 63;
    int n1 = p0 + lp, n2 = p0 + 64 + lp;
    bool v1 = n1 < HW, v2 = n2 < HW;
    const float* qb = g_q + ((long)b * GC + h * 32) * HW;

    float q1[32], q2[32];
    #pragma unroll
    for (int d = 0; d < 32; d++) {
        q1[d] = v1 ? qb[(long)d * HW + n1] : 0.f;
        q2[d] = v2 ? qb[(long)d * HW + n2] : 0.f;
    }
    float s1 = 0.f, s2 = 0.f;
    #pragma unroll
    for (int d = 0; d < 32; d++) {
        float km = kms[h * 32 + d];
        s1 += q1[d] * km;
        s2 += q2[d] * km;
    }
    float z1 = 1.f / (s1 + 1e-6f);
    float z2 = 1.f / (s2 + 1e-6f);

    float* ob = out + FEATS_BASE + ((long)b * 384 + h * 32) * HW;
    #pragma unroll
    for (int e4 = 0; e4 < 8; e4++) {
        float4 a1 = make_float4(0,0,0,0), a2 = make_float4(0,0,0,0);
        #pragma unroll
        for (int d = 0; d < 32; d++) {
            float4 kv = kvs4[(h * 32 + d) * 8 + e4];
            a1.x += q1[d] * kv.x; a1.y += q1[d] * kv.y;
            a1.z += q1[d] * kv.z; a1.w += q1[d] * kv.w;
            a2.x += q2[d] * kv.x; a2.y += q2[d] * kv.y;
            a2.z += q2[d] * kv.z; a2.w += q2[d] * kv.w;
        }
        int e = e4 * 4;
        if (v1) {
            ob[(long)(e+0) * HW + n1] = a1.x * z1;
            ob[(long)(e+1) * HW + n1] = a1.y * z1;
            ob[(long)(e+2) * HW + n1] = a1.z * z1;
            ob[(long)(e+3) * HW + n1] = a1.w * z1;
        }
        if (v2) {
            ob[(long)(e+0) * HW + n2] = a2.x * z2;
            ob[(long)(e+1) * HW + n2] = a2.y * z2;
            ob[(long)(e+2) * HW + n2] = a2.z * z2;
            ob[(long)(e+3) * HW + n2] = a2.w * z2;
        }
    }
}

// ---------------------------------------------------------------------------
__global__ __launch_bounds__(112) void dw3_kernel(const float* __restrict__ x,
                                                  const float* __restrict__ w,
                                                  const float* __restrict__ bias,
                                                  float* __restrict__ out) {
    __shared__ float tile[10][60];
    __shared__ float ws[9];
    int y0 = blockIdx.x * 8;
    int c = blockIdx.y, b = blockIdx.z;
    int tid = threadIdx.x;
    const float* in = x + ((long)b * CT + 2 * GC + c) * HW;

    if (tid < 9) ws[tid] = w[c * 9 + tid];
    for (int idx = tid; idx < 10 * 58; idx += 112) {
        int r = idx / 58, cc = idx % 58;
        int iy = y0 - 1 + r, ix = cc - 1;
        tile[r][cc] = (iy >= 0 && iy < H_ && ix >= 0 && ix < W_) ? in[iy * W_ + ix] : 0.f;
    }
    __syncthreads();

    int gx = tid % 14, gy = tid / 14;
    int xb = gx * 4;
    float bb = bias[c];
    float a0 = bb, a1 = bb, a2 = bb, a3 = bb;
    #pragma unroll
    for (int ky = 0; ky < 3; ky++) {
        const float* row = &tile[gy + ky][xb];
        float r[6];
        #pragma unroll
        for (int i = 0; i < 6; i++) r[i] = row[i];
        #pragma unroll
        for (int kx = 0; kx < 3; kx++) {
            float wv = ws[ky * 3 + kx];
            a0 += wv * r[kx + 0];
            a1 += wv * r[kx + 1];
            a2 += wv * r[kx + 2];
            a3 += wv * r[kx + 3];
        }
    }
    float* ob = out + FEATS_BASE + ((long)b * 384 + GC + c) * HW + (y0 + gy) * W_ + xb;
    ob[0] = a0; ob[1] = a1; ob[2] = a2; ob[3] = a3;
}

// ---------------------------------------------------------------------------
__global__ __launch_bounds__(112) void dw7_kernel(const float* __restrict__ x,
                                                  const float* __restrict__ w,
                                                  const float* __restrict__ bias,
                                                  float* __restrict__ out) {
    __shared__ float tile[14][64];
    __shared__ float ws[49];
    int y0 = blockIdx.x * 8;
    int c = blockIdx.y, b = blockIdx.z;
    int tid = threadIdx.x;
    const float* in = x + ((long)b * CT + 3 * GC + c) * HW;

    if (tid < 49) ws[tid] = w[c * 49 + tid];
    for (int idx = tid; idx < 14 * 62; idx += 112) {
        int r = idx / 62, cc = idx % 62;
        int iy = y0 - 3 + r, ix = cc - 3;
        tile[r][cc] = (iy >= 0 && iy < H_ && ix >= 0 && ix < W_) ? in[iy * W_ + ix] : 0.f;
    }
    __syncthreads();

    int gx = tid % 14, gy = tid / 14;
    int xb = gx * 4;
    float bb = bias[c];
    float a0 = bb, a1 = bb, a2 = bb, a3 = bb;
    #pragma unroll
    for (int ky = 0; ky < 7; ky++) {
        const float* row = &tile[gy + ky][xb];
        float r[10];
        #pragma unroll
        for (int i = 0; i < 10; i++) r[i] = row[i];
        #pragma unroll
        for (int kx = 0; kx < 7; kx++) {
            float wv = ws[ky * 7 + kx];
            a0 += wv * r[kx + 0];
            a1 += wv * r[kx + 1];
            a2 += wv * r[kx + 2];
            a3 += wv * r[kx + 3];
        }
    }
    float* ob = out + FEATS_BASE + ((long)b * 384 + 2 * GC + c) * HW + (y0 + gy) * W_ + xb;
    ob[0] = a0; ob[1] = a1; ob[2] = a2; ob[3] = a3;
}

// ---------------------------------------------------------------------------
extern "C" void kernel_launch(void* const* d_in, const int* in_sizes, int n_in,
                              void* d_out, int out_size) {
    const float* x     = (const float*)d_in[0];
    const float* w_dw1 = (const float*)d_in[1];
    const float* b_dw1 = (const float*)d_in[2];
    const float* w_dw2 = (const float*)d_in[3];
    const float* b_dw2 = (const float*)d_in[4];
    const float* w_qk  = (const float*)d_in[5];
    const float* b_qk  = (const float*)d_in[6];
    float* out = (float*)d_out;

    cudaFuncSetAttribute(qk_mma_kernel, cudaFuncAttributeMaxDynamicSharedMemorySize, SM_TOTAL);

    // qk_mma (with fused kv/ksum) at launch index 3 for ncu window.
    prep_kernel<<<512, 256>>>(w_qk);
    copy_mem_kernel<<<(B_ * GC * HW / 4 + 255) / 256, 256>>>((const float4*)x, (float4*)out);
    cvt_kernel<<<dim3(98, 4, B_), 256>>>(x);
    qk_mma_kernel<<<dim3(25, 2, B_), 256, SM_TOTAL>>>(x, b_qk);
    att_kernel<<<dim3(25, B_), 256>>>(out);
    dw3_kernel<<<dim3(7, GC, B_), 112>>>(x, w_dw1, b_dw1, out);
    dw7_kernel<<<dim3(7, GC, B_), 112>>>(x, w_dw2, b_dw2, out);
}

// round 16
// speedup vs baseline: 1.1216x; 1.1216x over previous
#include <cuda_runtime.h>
#include <cuda_bf16.h>
#include <cstdint>

#define B_  32
#define CT  512
#define GC  128
#define H_  56
#define W_  56
#define HW  3136
#define FEATS_BASE (B_*GC*HW)   // 12,845,056 floats: mem section size

// Scratch (device-global; allocation inside kernel_launch is forbidden)
__device__ float g_q[B_*GC*HW];                 // q post elu+1, channel-major [b][c][n]
__device__ float g_kv[B_*4*32*32];              // kv accumulators per (b,h,d,e)
__device__ float g_ksum[B_*4*32];               // k column sums per (b,h,d)
__device__ __nv_bfloat16 g_xt[(long)B_*HW*256]; // [b][px][ Xhi(128) | Xlo(128) ] bf16
__device__ __nv_bfloat16 g_wh[256*128];         // W hi bf16, [o][k]
__device__ __nv_bfloat16 g_wl[256*128];         // W lo bf16, [o][k]

__device__ __forceinline__ uint32_t smem_to_u32(const void* p) {
    uint32_t a;
    asm("{ .reg .u64 t; cvta.to.shared.u64 t, %1; cvt.u32.u64 %0, t; }" : "=r"(a) : "l"(p));
    return a;
}

#define LDMATRIX_X4(r0, r1, r2, r3, addr) \
    asm volatile("ldmatrix.sync.aligned.m8n8.x4.shared.b16 {%0,%1,%2,%3}, [%4];" \
                 : "=r"(r0), "=r"(r1), "=r"(r2), "=r"(r3) : "r"(addr))

#define MMA_16816(c0, c1, c2, c3, a0, a1, a2, a3, b0, b1) \
    asm volatile("mma.sync.aligned.m16n8k16.row.col.f32.bf16.bf16.f32 " \
                 "{%0,%1,%2,%3}, {%4,%5,%6,%7}, {%8,%9}, {%0,%1,%2,%3};" \
                 : "+f"(c0), "+f"(c1), "+f"(c2), "+f"(c3) \
                 : "r"(a0), "r"(a1), "r"(a2), "r"(a3), "r"(b0), "r"(b1))

// ---------------------------------------------------------------------------
__global__ __launch_bounds__(256) void prep_kernel(const float* __restrict__ wqk) {
    int i = blockIdx.x * 256 + threadIdx.x;
    if (i < 256 * 128) {
        float w = wqk[i];
        __nv_bfloat16 h = __float2bfloat16_rn(w);
        g_wh[i] = h;
        g_wl[i] = __float2bfloat16_rn(w - __bfloat162float(h));
    }
    if (i < B_*4*32*32) g_kv[i] = 0.f;
    if (i < B_*4*32)    g_ksum[i] = 0.f;
}

// ---------------------------------------------------------------------------
__global__ void copy_mem_kernel(const float4* __restrict__ x, float4* __restrict__ out) {
    long i = (long)blockIdx.x * blockDim.x + threadIdx.x;
    const long total = (long)B_ * GC * HW / 4;
    if (i >= total) return;
    const int per_b = GC * HW / 4;
    int b = (int)(i / per_b);
    int r = (int)(i % per_b);
    out[i] = x[(long)b * (CT * HW / 4) + r];
}

// ---------------------------------------------------------------------------
// Transpose + split-bf16 convert: x[b][128+c][px] -> g_xt[b][px][ hi(128) | lo(128) ]
__global__ __launch_bounds__(256) void cvt_kernel(const float* __restrict__ x) {
    __shared__ float tile[32][33];
    int b = blockIdx.z;
    int ch0 = blockIdx.y * 32;
    int px0 = blockIdx.x * 32;
    int tid = threadIdx.x;
    int tx = tid & 31, ty = tid >> 5;

    const float* src = x + ((long)b * CT + GC + ch0) * HW + px0;
    #pragma unroll
    for (int r = 0; r < 4; r++) {
        int c = ty + r * 8;
        tile[c][tx] = src[(long)c * HW + tx];
    }
    __syncthreads();

    uint32_t* dstu = reinterpret_cast<uint32_t*>(g_xt);
    #pragma unroll
    for (int r = 0; r < 4; r++) {
        int pxl = ty + r * 8;
        long rowBase = ((long)b * HW + px0 + pxl) * 128;
        int pi = (tx < 16) ? tx : (tx - 16);
        float f0 = tile[2*pi][pxl];
        float f1 = tile[2*pi+1][pxl];
        __nv_bfloat16 h0 = __float2bfloat16_rn(f0);
        __nv_bfloat16 h1 = __float2bfloat16_rn(f1);
        uint32_t val;
        if (tx < 16) {
            val = (uint32_t)__bfloat16_as_ushort(h0) | ((uint32_t)__bfloat16_as_ushort(h1) << 16);
            dstu[rowBase + (ch0 >> 1) + pi] = val;
        } else {
            __nv_bfloat16 l0 = __float2bfloat16_rn(f0 - __bfloat162float(h0));
            __nv_bfloat16 l1 = __float2bfloat16_rn(f1 - __bfloat162float(h1));
            val = (uint32_t)__bfloat16_as_ushort(l0) | ((uint32_t)__bfloat16_as_ushort(l1) << 16);
            dstu[rowBase + 64 + (ch0 >> 1) + pi] = val;
        }
    }
}

// ---------------------------------------------------------------------------
// qk GEMM via mma.sync split-bf16 (R13 version — fused kv/ksum in k branch).
#define BS_STRIDE 264
#define WC_STRIDE 24
#define SM_BS     0
#define SM_WC     (128 * BS_STRIDE * 2)      // 67584
#define WC_HALF   (128 * WC_STRIDE * 2)      // 6144
#define SM_VS     67584                      // V staging (aliases WC; used strictly after mainloop)
#define VS_STR    68
#define SM_TOTAL  (SM_VS + 128 * VS_STR * 4) // 102400
#define DS_STR    132

__global__ __launch_bounds__(256, 2) void qk_mma_kernel(const float* __restrict__ x,
                                                        const float* __restrict__ bqk) {
    extern __shared__ __align__(16) char sm[];
    __nv_bfloat16* Bs = (__nv_bfloat16*)(sm + SM_BS);
    float* Ds = (float*)sm;                 // union; used after compute
    float* Vs = (float*)(sm + SM_VS);       // k-branch V staging

    int b = blockIdx.z;
    int oBase = blockIdx.y * 128;
    int pBase = blockIdx.x * 128;
    int tid = threadIdx.x;
    int wid = tid >> 5, lane = tid & 31;
    int oSub = (wid & 3) * 32;
    int nSub = (wid >> 2) * 64;

    // ---- load B tile: 128 px rows x 256 bf16 (hi|lo), guarded
    {
        const uint4* src = (const uint4*)(g_xt + ((long)b * HW + pBase) * 256);
        const uint4 z4 = make_uint4(0u, 0u, 0u, 0u);
        #pragma unroll
        for (int it = 0; it < 16; it++) {
            int idx = tid + it * 256;
            int row = idx >> 5;
            int j = idx & 31;
            uint4 v = (pBase + row < HW) ? src[row * 32 + j] : z4;
            *(uint4*)(Bs + row * BS_STRIDE + j * 8) = v;
        }
    }

    float acc[2][8][4];
    #pragma unroll
    for (int mt = 0; mt < 2; mt++)
        #pragma unroll
        for (int nt = 0; nt < 8; nt++)
            #pragma unroll
            for (int c = 0; c < 4; c++) acc[mt][nt][c] = 0.f;

    int wrow = tid >> 1, wseg = tid & 1;
    const uint4* ghp = (const uint4*)(g_wh + (long)(oBase + wrow) * 128 + wseg * 8);
    const uint4* glp = (const uint4*)(g_wl + (long)(oBase + wrow) * 128 + wseg * 8);
    uint4* sh = (uint4*)(sm + SM_WC + wrow * (WC_STRIDE * 2) + wseg * 16);
    uint4* sl = (uint4*)(sm + SM_WC + WC_HALF + wrow * (WC_STRIDE * 2) + wseg * 16);

    uint32_t aOff = (uint32_t)((oSub + (lane & 15)) * (WC_STRIDE * 2) + (lane >> 4) * 16);
    uint32_t aAddrH = smem_to_u32(sm + SM_WC) + aOff;
    uint32_t aAddrL = aAddrH + WC_HALF;

    uint32_t g = (uint32_t)(lane >> 3);
    uint32_t bRow = (uint32_t)(nSub + ((g >> 1) << 3) + (lane & 7));
    uint32_t bAddr0 = smem_to_u32(Bs) + bRow * (BS_STRIDE * 2) + (g & 1) * 16;

    uint4 ph = ghp[0];
    uint4 pl = glp[0];

    #pragma unroll
    for (int ks = 0; ks < 8; ks++) {
        __syncthreads();
        *sh = ph;
        *sl = pl;
        __syncthreads();
        if (ks < 7) {
            ph = ghp[(ks + 1) * 2];
            pl = glp[(ks + 1) * 2];
        }

        uint32_t aH[2][4], aL[2][4];
        #pragma unroll
        for (int mt = 0; mt < 2; mt++) {
            LDMATRIX_X4(aH[mt][0], aH[mt][1], aH[mt][2], aH[mt][3],
                        aAddrH + (uint32_t)(mt * 16 * (WC_STRIDE * 2)));
            LDMATRIX_X4(aL[mt][0], aL[mt][1], aL[mt][2], aL[mt][3],
                        aAddrL + (uint32_t)(mt * 16 * (WC_STRIDE * 2)));
        }
        int kc = ks * 16;
        uint32_t bkbH = (uint32_t)(kc * 2);
        uint32_t bkbL = (uint32_t)((128 + kc) * 2);

        #pragma unroll
        for (int m = 0; m < 4; m++) {
            uint32_t bOff = bAddr0 + (uint32_t)(m * 16 * (BS_STRIDE * 2));
            uint32_t hF[4], lF[4];
            LDMATRIX_X4(hF[0], hF[1], hF[2], hF[3], bOff + bkbH);
            LDMATRIX_X4(lF[0], lF[1], lF[2], lF[3], bOff + bkbL);
            #pragma unroll
            for (int sub = 0; sub < 2; sub++) {
                int nt = m * 2 + sub;
                uint32_t bh0 = hF[sub * 2], bh1 = hF[sub * 2 + 1];
                uint32_t bl0 = lF[sub * 2], bl1 = lF[sub * 2 + 1];
                #pragma unroll
                for (int mt = 0; mt < 2; mt++) {
                    MMA_16816(acc[mt][nt][0], acc[mt][nt][1], acc[mt][nt][2], acc[mt][nt][3],
                              aH[mt][0], aH[mt][1], aH[mt][2], aH[mt][3], bh0, bh1);
                    MMA_16816(acc[mt][nt][0], acc[mt][nt][1], acc[mt][nt][2], acc[mt][nt][3],
                              aH[mt][0], aH[mt][1], aH[mt][2], aH[mt][3], bl0, bl1);
                    MMA_16816(acc[mt][nt][0], acc[mt][nt][1], acc[mt][nt][2], acc[mt][nt][3],
                              aL[mt][0], aL[mt][1], aL[mt][2], aL[mt][3], bh0, bh1);
                }
            }
        }
    }
    __syncthreads();   // done with Bs/Wc; alias as Ds

    if (blockIdx.y == 0) {
        // ---- q epilogue: Ds[o][n] stride 132, channel-major coalesced store
        #pragma unroll
        for (int mt = 0; mt < 2; mt++) {
            #pragma unroll
            for (int half = 0; half < 2; half++) {
                int row = oSub + mt * 16 + (lane >> 2) + half * 8;
                float bias = bqk[row];
                #pragma unroll
                for (int nt = 0; nt < 8; nt++) {
                    int col = nSub + nt * 8 + (lane & 3) * 2;
                    float v0 = acc[mt][nt][half * 2 + 0] + bias;
                    float v1 = acc[mt][nt][half * 2 + 1] + bias;
                    Ds[row * DS_STR + col]     = (v0 > 0.f) ? (v0 + 1.f) : __expf(v0);
                    Ds[row * DS_STR + col + 1] = (v1 > 0.f) ? (v1 + 1.f) : __expf(v1);
                }
            }
        }
        __syncthreads();
        float* base = g_q + (long)b * GC * HW + pBase;
        #pragma unroll
        for (int it = 0; it < 16; it++) {
            int idx = tid + it * 256;
            int o = idx >> 5, c4 = idx & 31;
            if (pBase + c4 * 4 < HW) {
                float4 v = *(float4*)(Ds + o * DS_STR + c4 * 4);
                *(float4*)(base + (long)o * HW + c4 * 4) = v;
            }
        }
    } else {
        // ---- k epilogue: Ds[px][c] (zeroed for invalid px), then fused
        //      kv/ksum reduction with V staged 64 channels at a time.
        #pragma unroll
        for (int mt = 0; mt < 2; mt++) {
            #pragma unroll
            for (int half = 0; half < 2; half++) {
                int row = oSub + mt * 16 + (lane >> 2) + half * 8;
                float bias = bqk[GC + row];
                #pragma unroll
                for (int nt = 0; nt < 8; nt++) {
                    int col = nSub + nt * 8 + (lane & 3) * 2;
                    bool ok = (pBase + col) < HW;   // col,col+1 same validity
                    float v0 = acc[mt][nt][half * 2 + 0] + bias;
                    float v1 = acc[mt][nt][half * 2 + 1] + bias;
                    v0 = (v0 > 0.f) ? (v0 + 1.f) : __expf(v0);
                    v1 = (v1 > 0.f) ? (v1 + 1.f) : __expf(v1);
                    Ds[col * DS_STR + row]       = ok ? v0 : 0.f;
                    Ds[(col + 1) * DS_STR + row] = ok ? v1 : 0.f;
                }
            }
        }

        int hh = tid >> 7;              // head within pair
        int t2 = tid & 127;
        int d0 = (t2 >> 3) * 2;         // 0,2,..,30
        int e0 = (t2 & 7) * 4;          // 0,4,..,28
        bool doKs = (e0 == 0);

        #pragma unroll
        for (int half = 0; half < 2; half++) {
            __syncthreads();            // Ds ready (half 0) / Vs free (half 1)
            const float* Vb = x + ((long)b * CT + GC + half * 64) * HW;
            #pragma unroll
            for (int it = 0; it < 32; it++) {
                int idx = tid + it * 256;       // 8192 = 64c x 128p
                int c = idx >> 7, p = idx & 127;
                Vs[p * VS_STR + c] = (pBase + p < HW) ? Vb[(long)c * HW + pBase + p] : 0.f;
            }
            __syncthreads();

            int head = half * 2 + hh;
            const float* Dk = Ds + head * 32 + d0;
            const float* Vv = Vs + hh * 32 + e0;
            float a0[4] = {0,0,0,0}, a1[4] = {0,0,0,0};
            float ks0 = 0.f, ks1 = 0.f;
            #pragma unroll 8
            for (int p = 0; p < 128; p++) {
                float2 k2 = *(const float2*)(Dk + p * DS_STR);
                float4 v4 = *(const float4*)(Vv + p * VS_STR);
                a0[0] += k2.x * v4.x; a0[1] += k2.x * v4.y;
                a0[2] += k2.x * v4.z; a0[3] += k2.x * v4.w;
                a1[0] += k2.y * v4.x; a1[1] += k2.y * v4.y;
                a1[2] += k2.y * v4.z; a1[3] += k2.y * v4.w;
                if (doKs) { ks0 += k2.x; ks1 += k2.y; }
            }
            float* kvdst = g_kv + (((long)(b * 4 + head) * 32 + d0) * 32 + e0);
            #pragma unroll
            for (int j = 0; j < 4; j++) {
                atomicAdd(kvdst + j, a0[j]);
                atomicAdd(kvdst + 32 + j, a1[j]);
            }
            if (doKs) {
                atomicAdd(g_ksum + (b * 4 + head) * 32 + d0,     ks0);
                atomicAdd(g_ksum + (b * 4 + head) * 32 + d0 + 1, ks1);
            }
        }
    }
}

// ---------------------------------------------------------------------------
// att: q read channel-major (lane-coalesced over n).
__global__ __launch_bounds__(256) void att_kernel(float* __restrict__ out) {
    __shared__ float4 kvs4[1024];
    __shared__ float  kms[128];
    int b = blockIdx.y;
    int p0 = blockIdx.x * 128;
    int tid = threadIdx.x;
    const float invHW = 1.f / (float)HW;
    const float4* kvsrc = (const float4*)(g_kv + (long)b * 4096);
    for (int idx = tid; idx < 1024; idx += 256) {
        float4 v = kvsrc[idx];
        v.x *= invHW; v.y *= invHW; v.z *= invHW; v.w *= invHW;
        kvs4[idx] = v;
    }
    if (tid < 128) kms[tid] = g_ksum[b * 128 + tid] * invHW;
    __syncthreads();

    int h = tid >> 6, lp = tid & 63;
    int n1 = p0 + lp, n2 = p0 + 64 + lp;
    bool v1 = n1 < HW, v2 = n2 < HW;
    const float* qb = g_q + ((long)b * GC + h * 32) * HW;

    float q1[32], q2[32];
    #pragma unroll
    for (int d = 0; d < 32; d++) {
        q1[d] = v1 ? qb[(long)d * HW + n1] : 0.f;
        q2[d] = v2 ? qb[(long)d * HW + n2] : 0.f;
    }
    float s1 = 0.f, s2 = 0.f;
    #pragma unroll
    for (int d = 0; d < 32; d++) {
        float km = kms[h * 32 + d];
        s1 += q1[d] * km;
        s2 += q2[d] * km;
    }
    float z1 = 1.f / (s1 + 1e-6f);
    float z2 = 1.f / (s2 + 1e-6f);

    float* ob = out + FEATS_BASE + ((long)b * 384 + h * 32) * HW;
    #pragma unroll
    for (int e4 = 0; e4 < 8; e4++) {
        float4 a1 = make_float4(0,0,0,0), a2 = make_float4(0,0,0,0);
        #pragma unroll
        for (int d = 0; d < 32; d++) {
            float4 kv = kvs4[(h * 32 + d) * 8 + e4];
            a1.x += q1[d] * kv.x; a1.y += q1[d] * kv.y;
            a1.z += q1[d] * kv.z; a1.w += q1[d] * kv.w;
            a2.x += q2[d] * kv.x; a2.y += q2[d] * kv.y;
            a2.z += q2[d] * kv.z; a2.w += q2[d] * kv.w;
        }
        int e = e4 * 4;
        if (v1) {
            ob[(long)(e+0) * HW + n1] = a1.x * z1;
            ob[(long)(e+1) * HW + n1] = a1.y * z1;
            ob[(long)(e+2) * HW + n1] = a1.z * z1;
            ob[(long)(e+3) * HW + n1] = a1.w * z1;
        }
        if (v2) {
            ob[(long)(e+0) * HW + n2] = a2.x * z2;
            ob[(long)(e+1) * HW + n2] = a2.y * z2;
            ob[(long)(e+2) * HW + n2] = a2.z * z2;
            ob[(long)(e+3) * HW + n2] = a2.w * z2;
        }
    }
}

// ---------------------------------------------------------------------------
__global__ __launch_bounds__(112) void dw3_kernel(const float* __restrict__ x,
                                                  const float* __restrict__ w,
                                                  const float* __restrict__ bias,
                                                  float* __restrict__ out) {
    __shared__ float tile[10][60];
    __shared__ float ws[9];
    int y0 = blockIdx.x * 8;
    int c = blockIdx.y, b = blockIdx.z;
    int tid = threadIdx.x;
    const float* in = x + ((long)b * CT + 2 * GC + c) * HW;

    if (tid < 9) ws[tid] = w[c * 9 + tid];
    for (int idx = tid; idx < 10 * 58; idx += 112) {
        int r = idx / 58, cc = idx % 58;
        int iy = y0 - 1 + r, ix = cc - 1;
        tile[r][cc] = (iy >= 0 && iy < H_ && ix >= 0 && ix < W_) ? in[iy * W_ + ix] : 0.f;
    }
    __syncthreads();

    int gx = tid % 14, gy = tid / 14;
    int xb = gx * 4;
    float bb = bias[c];
    float a0 = bb, a1 = bb, a2 = bb, a3 = bb;
    #pragma unroll
    for (int ky = 0; ky < 3; ky++) {
        const float* row = &tile[gy + ky][xb];
        float r[6];
        #pragma unroll
        for (int i = 0; i < 6; i++) r[i] = row[i];
        #pragma unroll
        for (int kx = 0; kx < 3; kx++) {
            float wv = ws[ky * 3 + kx];
            a0 += wv * r[kx + 0];
            a1 += wv * r[kx + 1];
            a2 += wv * r[kx + 2];
            a3 += wv * r[kx + 3];
        }
    }
    float* ob = out + FEATS_BASE + ((long)b * 384 + GC + c) * HW + (y0 + gy) * W_ + xb;
    ob[0] = a0; ob[1] = a1; ob[2] = a2; ob[3] = a3;
}

// ---------------------------------------------------------------------------
__global__ __launch_bounds__(112) void dw7_kernel(const float* __restrict__ x,
                                                  const float* __restrict__ w,
                                                  const float* __restrict__ bias,
                                                  float* __restrict__ out) {
    __shared__ float tile[14][64];
    __shared__ float ws[49];
    int y0 = blockIdx.x * 8;
    int c = blockIdx.y, b = blockIdx.z;
    int tid = threadIdx.x;
    const float* in = x + ((long)b * CT + 3 * GC + c) * HW;

    if (tid < 49) ws[tid] = w[c * 49 + tid];
    for (int idx = tid; idx < 14 * 62; idx += 112) {
        int r = idx / 62, cc = idx % 62;
        int iy = y0 - 3 + r, ix = cc - 3;
        tile[r][cc] = (iy >= 0 && iy < H_ && ix >= 0 && ix < W_) ? in[iy * W_ + ix] : 0.f;
    }
    __syncthreads();

    int gx = tid % 14, gy = tid / 14;
    int xb = gx * 4;
    float bb = bias[c];
    float a0 = bb, a1 = bb, a2 = bb, a3 = bb;
    #pragma unroll
    for (int ky = 0; ky < 7; ky++) {
        const float* row = &tile[gy + ky][xb];
        float r[10];
        #pragma unroll
        for (int i = 0; i < 10; i++) r[i] = row[i];
        #pragma unroll
        for (int kx = 0; kx < 7; kx++) {
            float wv = ws[ky * 7 + kx];
            a0 += wv * r[kx + 0];
            a1 += wv * r[kx + 1];
            a2 += wv * r[kx + 2];
            a3 += wv * r[kx + 3];
        }
    }
    float* ob = out + FEATS_BASE + ((long)b * 384 + 2 * GC + c) * HW + (y0 + gy) * W_ + xb;
    ob[0] = a0; ob[1] = a1; ob[2] = a2; ob[3] = a3;
}

// ---------------------------------------------------------------------------
extern "C" void kernel_launch(void* const* d_in, const int* in_sizes, int n_in,
                              void* d_out, int out_size) {
    const float* x     = (const float*)d_in[0];
    const float* w_dw1 = (const float*)d_in[1];
    const float* b_dw1 = (const float*)d_in[2];
    const float* w_dw2 = (const float*)d_in[3];
    const float* b_dw2 = (const float*)d_in[4];
    const float* w_qk  = (const float*)d_in[5];
    const float* b_qk  = (const float*)d_in[6];
    float* out = (float*)d_out;

    cudaFuncSetAttribute(qk_mma_kernel, cudaFuncAttributeMaxDynamicSharedMemorySize, SM_TOTAL);

    // Fork a side stream for the independent branch {copy_mem, dw3, dw7};
    // the attention chain {prep, cvt, qk_mma, att} stays on the main stream.
    // Graph capture supports this via event fork/join.
    cudaStream_t s1;
    cudaStreamCreate(&s1);
    cudaEvent_t eFork, eJoin;
    cudaEventCreateWithFlags(&eFork, cudaEventDisableTiming);
    cudaEventCreateWithFlags(&eJoin, cudaEventDisableTiming);

    cudaEventRecord(eFork, 0);
    cudaStreamWaitEvent(s1, eFork, 0);

    // side branch (independent of attention chain)
    copy_mem_kernel<<<(B_ * GC * HW / 4 + 255) / 256, 256, 0, s1>>>((const float4*)x, (float4*)out);
    dw3_kernel<<<dim3(7, GC, B_), 112, 0, s1>>>(x, w_dw1, b_dw1, out);
    dw7_kernel<<<dim3(7, GC, B_), 112, 0, s1>>>(x, w_dw2, b_dw2, out);
    cudaEventRecord(eJoin, s1);

    // main chain
    prep_kernel<<<512, 256>>>(w_qk);
    cvt_kernel<<<dim3(98, 4, B_), 256>>>(x);
    qk_mma_kernel<<<dim3(25, 2, B_), 256, SM_TOTAL>>>(x, b_qk);
    att_kernel<<<dim3(25, B_), 256>>>(out);

    cudaStreamWaitEvent(0, eJoin, 0);

    cudaEventDestroy(eFork);
    cudaEventDestroy(eJoin);
    cudaStreamDestroy(s1);
}

// round 17
// speedup vs baseline: 1.1353x; 1.0122x over previous
#include <cuda_runtime.h>
#include <cuda_bf16.h>
#include <cstdint>

#define B_  32
#define CT  512
#define GC  128
#define H_  56
#define W_  56
#define HW  3136
#define FEATS_BASE (B_*GC*HW)   // 12,845,056 floats: mem section size

// Scratch (device-global; allocation inside kernel_launch is forbidden)
__device__ float g_q[B_*GC*HW];                 // q post elu+1, channel-major [b][c][n]
__device__ float g_kv[B_*4*32*32];              // kv accumulators per (b,h,d,e)
__device__ float g_ksum[B_*4*32];               // k column sums per (b,h,d)
__device__ __nv_bfloat16 g_xt[(long)B_*HW*256]; // [b][px][ Xhi(128) | Xlo(128) ] bf16
__device__ __nv_bfloat16 g_wh[256*128];         // W hi bf16, [o][k]
__device__ __nv_bfloat16 g_wl[256*128];         // W lo bf16, [o][k]

__device__ __forceinline__ uint32_t smem_to_u32(const void* p) {
    uint32_t a;
    asm("{ .reg .u64 t; cvta.to.shared.u64 t, %1; cvt.u32.u64 %0, t; }" : "=r"(a) : "l"(p));
    return a;
}

#define LDMATRIX_X4(r0, r1, r2, r3, addr) \
    asm volatile("ldmatrix.sync.aligned.m8n8.x4.shared.b16 {%0,%1,%2,%3}, [%4];" \
                 : "=r"(r0), "=r"(r1), "=r"(r2), "=r"(r3) : "r"(addr))

#define MMA_16816(c0, c1, c2, c3, a0, a1, a2, a3, b0, b1) \
    asm volatile("mma.sync.aligned.m16n8k16.row.col.f32.bf16.bf16.f32 " \
                 "{%0,%1,%2,%3}, {%4,%5,%6,%7}, {%8,%9}, {%0,%1,%2,%3};" \
                 : "+f"(c0), "+f"(c1), "+f"(c2), "+f"(c3) \
                 : "r"(a0), "r"(a1), "r"(a2), "r"(a3), "r"(b0), "r"(b1))

// ---------------------------------------------------------------------------
__global__ __launch_bounds__(256) void prep_kernel(const float* __restrict__ wqk) {
    int i = blockIdx.x * 256 + threadIdx.x;
    if (i < 256 * 128) {
        float w = wqk[i];
        __nv_bfloat16 h = __float2bfloat16_rn(w);
        g_wh[i] = h;
        g_wl[i] = __float2bfloat16_rn(w - __bfloat162float(h));
    }
    if (i < B_*4*32*32) g_kv[i] = 0.f;
    if (i < B_*4*32)    g_ksum[i] = 0.f;
}

// ---------------------------------------------------------------------------
__global__ void copy_mem_kernel(const float4* __restrict__ x, float4* __restrict__ out) {
    long i = (long)blockIdx.x * blockDim.x + threadIdx.x;
    const long total = (long)B_ * GC * HW / 4;
    if (i >= total) return;
    const int per_b = GC * HW / 4;
    int b = (int)(i / per_b);
    int r = (int)(i % per_b);
    out[i] = x[(long)b * (CT * HW / 4) + r];
}

// ---------------------------------------------------------------------------
// Transpose + split-bf16 convert: x[b][128+c][px] -> g_xt[b][px][ hi(128) | lo(128) ]
__global__ __launch_bounds__(256) void cvt_kernel(const float* __restrict__ x) {
    __shared__ float tile[32][33];
    int b = blockIdx.z;
    int ch0 = blockIdx.y * 32;
    int px0 = blockIdx.x * 32;
    int tid = threadIdx.x;
    int tx = tid & 31, ty = tid >> 5;

    const float* src = x + ((long)b * CT + GC + ch0) * HW + px0;
    #pragma unroll
    for (int r = 0; r < 4; r++) {
        int c = ty + r * 8;
        tile[c][tx] = src[(long)c * HW + tx];
    }
    __syncthreads();

    uint32_t* dstu = reinterpret_cast<uint32_t*>(g_xt);
    #pragma unroll
    for (int r = 0; r < 4; r++) {
        int pxl = ty + r * 8;
        long rowBase = ((long)b * HW + px0 + pxl) * 128;
        int pi = (tx < 16) ? tx : (tx - 16);
        float f0 = tile[2*pi][pxl];
        float f1 = tile[2*pi+1][pxl];
        __nv_bfloat16 h0 = __float2bfloat16_rn(f0);
        __nv_bfloat16 h1 = __float2bfloat16_rn(f1);
        uint32_t val;
        if (tx < 16) {
            val = (uint32_t)__bfloat16_as_ushort(h0) | ((uint32_t)__bfloat16_as_ushort(h1) << 16);
            dstu[rowBase + (ch0 >> 1) + pi] = val;
        } else {
            __nv_bfloat16 l0 = __float2bfloat16_rn(f0 - __bfloat162float(h0));
            __nv_bfloat16 l1 = __float2bfloat16_rn(f1 - __bfloat162float(h1));
            val = (uint32_t)__bfloat16_as_ushort(l0) | ((uint32_t)__bfloat16_as_ushort(l1) << 16);
            dstu[rowBase + 64 + (ch0 >> 1) + pi] = val;
        }
    }
}

// ---------------------------------------------------------------------------
// qk GEMM via mma.sync split-bf16 (R13 body; kMode selects q or k branch).
#define BS_STRIDE 264
#define WC_STRIDE 24
#define SM_BS     0
#define SM_WC     (128 * BS_STRIDE * 2)      // 67584
#define WC_HALF   (128 * WC_STRIDE * 2)      // 6144
#define SM_VS     67584                      // V staging (aliases WC; used strictly after mainloop)
#define VS_STR    68
#define SM_TOTAL  (SM_VS + 128 * VS_STR * 4) // 102400
#define DS_STR    132

__global__ __launch_bounds__(256, 2) void qk_mma_kernel(const float* __restrict__ x,
                                                        const float* __restrict__ bqk,
                                                        const int kMode) {
    extern __shared__ __align__(16) char sm[];
    __nv_bfloat16* Bs = (__nv_bfloat16*)(sm + SM_BS);
    float* Ds = (float*)sm;                 // union; used after compute
    float* Vs = (float*)(sm + SM_VS);       // k-branch V staging

    int b = blockIdx.z;
    int oBase = kMode * 128;
    int pBase = blockIdx.x * 128;
    int tid = threadIdx.x;
    int wid = tid >> 5, lane = tid & 31;
    int oSub = (wid & 3) * 32;
    int nSub = (wid >> 2) * 64;

    // ---- load B tile: 128 px rows x 256 bf16 (hi|lo), guarded
    {
        const uint4* src = (const uint4*)(g_xt + ((long)b * HW + pBase) * 256);
        const uint4 z4 = make_uint4(0u, 0u, 0u, 0u);
        #pragma unroll
        for (int it = 0; it < 16; it++) {
            int idx = tid + it * 256;
            int row = idx >> 5;
            int j = idx & 31;
            uint4 v = (pBase + row < HW) ? src[row * 32 + j] : z4;
            *(uint4*)(Bs + row * BS_STRIDE + j * 8) = v;
        }
    }

    float acc[2][8][4];
    #pragma unroll
    for (int mt = 0; mt < 2; mt++)
        #pragma unroll
        for (int nt = 0; nt < 8; nt++)
            #pragma unroll
            for (int c = 0; c < 4; c++) acc[mt][nt][c] = 0.f;

    int wrow = tid >> 1, wseg = tid & 1;
    const uint4* ghp = (const uint4*)(g_wh + (long)(oBase + wrow) * 128 + wseg * 8);
    const uint4* glp = (const uint4*)(g_wl + (long)(oBase + wrow) * 128 + wseg * 8);
    uint4* sh = (uint4*)(sm + SM_WC + wrow * (WC_STRIDE * 2) + wseg * 16);
    uint4* sl = (uint4*)(sm + SM_WC + WC_HALF + wrow * (WC_STRIDE * 2) + wseg * 16);

    uint32_t aOff = (uint32_t)((oSub + (lane & 15)) * (WC_STRIDE * 2) + (lane >> 4) * 16);
    uint32_t aAddrH = smem_to_u32(sm + SM_WC) + aOff;
    uint32_t aAddrL = aAddrH + WC_HALF;

    uint32_t g = (uint32_t)(lane >> 3);
    uint32_t bRow = (uint32_t)(nSub + ((g >> 1) << 3) + (lane & 7));
    uint32_t bAddr0 = smem_to_u32(Bs) + bRow * (BS_STRIDE * 2) + (g & 1) * 16;

    uint4 ph = ghp[0];
    uint4 pl = glp[0];

    #pragma unroll
    for (int ks = 0; ks < 8; ks++) {
        __syncthreads();
        *sh = ph;
        *sl = pl;
        __syncthreads();
        if (ks < 7) {
            ph = ghp[(ks + 1) * 2];
            pl = glp[(ks + 1) * 2];
        }

        uint32_t aH[2][4], aL[2][4];
        #pragma unroll
        for (int mt = 0; mt < 2; mt++) {
            LDMATRIX_X4(aH[mt][0], aH[mt][1], aH[mt][2], aH[mt][3],
                        aAddrH + (uint32_t)(mt * 16 * (WC_STRIDE * 2)));
            LDMATRIX_X4(aL[mt][0], aL[mt][1], aL[mt][2], aL[mt][3],
                        aAddrL + (uint32_t)(mt * 16 * (WC_STRIDE * 2)));
        }
        int kc = ks * 16;
        uint32_t bkbH = (uint32_t)(kc * 2);
        uint32_t bkbL = (uint32_t)((128 + kc) * 2);

        #pragma unroll
        for (int m = 0; m < 4; m++) {
            uint32_t bOff = bAddr0 + (uint32_t)(m * 16 * (BS_STRIDE * 2));
            uint32_t hF[4], lF[4];
            LDMATRIX_X4(hF[0], hF[1], hF[2], hF[3], bOff + bkbH);
            LDMATRIX_X4(lF[0], lF[1], lF[2], lF[3], bOff + bkbL);
            #pragma unroll
            for (int sub = 0; sub < 2; sub++) {
                int nt = m * 2 + sub;
                uint32_t bh0 = hF[sub * 2], bh1 = hF[sub * 2 + 1];
                uint32_t bl0 = lF[sub * 2], bl1 = lF[sub * 2 + 1];
                #pragma unroll
                for (int mt = 0; mt < 2; mt++) {
                    MMA_16816(acc[mt][nt][0], acc[mt][nt][1], acc[mt][nt][2], acc[mt][nt][3],
                              aH[mt][0], aH[mt][1], aH[mt][2], aH[mt][3], bh0, bh1);
                    MMA_16816(acc[mt][nt][0], acc[mt][nt][1], acc[mt][nt][2], acc[mt][nt][3],
                              aH[mt][0], aH[mt][1], aH[mt][2], aH[mt][3], bl0, bl1);
                    MMA_16816(acc[mt][nt][0], acc[mt][nt][1], acc[mt][nt][2], acc[mt][nt][3],
                              aL[mt][0], aL[mt][1], aL[mt][2], aL[mt][3], bh0, bh1);
                }
            }
        }
    }
    __syncthreads();   // done with Bs/Wc; alias as Ds

    if (kMode == 0) {
        // ---- q epilogue: Ds[o][n] stride 132, channel-major coalesced store
        #pragma unroll
        for (int mt = 0; mt < 2; mt++) {
            #pragma unroll
            for (int half = 0; half < 2; half++) {
                int row = oSub + mt * 16 + (lane >> 2) + half * 8;
                float bias = bqk[row];
                #pragma unroll
                for (int nt = 0; nt < 8; nt++) {
                    int col = nSub + nt * 8 + (lane & 3) * 2;
                    float v0 = acc[mt][nt][half * 2 + 0] + bias;
                    float v1 = acc[mt][nt][half * 2 + 1] + bias;
                    Ds[row * DS_STR + col]     = (v0 > 0.f) ? (v0 + 1.f) : __expf(v0);
                    Ds[row * DS_STR + col + 1] = (v1 > 0.f) ? (v1 + 1.f) : __expf(v1);
                }
            }
        }
        __syncthreads();
        float* base = g_q + (long)b * GC * HW + pBase;
        #pragma unroll
        for (int it = 0; it < 16; it++) {
            int idx = tid + it * 256;
            int o = idx >> 5, c4 = idx & 31;
            if (pBase + c4 * 4 < HW) {
                float4 v = *(float4*)(Ds + o * DS_STR + c4 * 4);
                *(float4*)(base + (long)o * HW + c4 * 4) = v;
            }
        }
    } else {
        // ---- k epilogue: Ds[px][c] (zeroed for invalid px), then fused
        //      kv/ksum reduction with V staged 64 channels at a time.
        #pragma unroll
        for (int mt = 0; mt < 2; mt++) {
            #pragma unroll
            for (int half = 0; half < 2; half++) {
                int row = oSub + mt * 16 + (lane >> 2) + half * 8;
                float bias = bqk[GC + row];
                #pragma unroll
                for (int nt = 0; nt < 8; nt++) {
                    int col = nSub + nt * 8 + (lane & 3) * 2;
                    bool ok = (pBase + col) < HW;   // col,col+1 same validity
                    float v0 = acc[mt][nt][half * 2 + 0] + bias;
                    float v1 = acc[mt][nt][half * 2 + 1] + bias;
                    v0 = (v0 > 0.f) ? (v0 + 1.f) : __expf(v0);
                    v1 = (v1 > 0.f) ? (v1 + 1.f) : __expf(v1);
                    Ds[col * DS_STR + row]       = ok ? v0 : 0.f;
                    Ds[(col + 1) * DS_STR + row] = ok ? v1 : 0.f;
                }
            }
        }

        int hh = tid >> 7;              // head within pair
        int t2 = tid & 127;
        int d0 = (t2 >> 3) * 2;         // 0,2,..,30
        int e0 = (t2 & 7) * 4;          // 0,4,..,28
        bool doKs = (e0 == 0);

        #pragma unroll
        for (int half = 0; half < 2; half++) {
            __syncthreads();            // Ds ready (half 0) / Vs free (half 1)
            const float* Vb = x + ((long)b * CT + GC + half * 64) * HW;
            #pragma unroll
            for (int it = 0; it < 32; it++) {
                int idx = tid + it * 256;       // 8192 = 64c x 128p
                int c = idx >> 7, p = idx & 127;
                Vs[p * VS_STR + c] = (pBase + p < HW) ? Vb[(long)c * HW + pBase + p] : 0.f;
            }
            __syncthreads();

            int head = half * 2 + hh;
            const float* Dk = Ds + head * 32 + d0;
            const float* Vv = Vs + hh * 32 + e0;
            float a0[4] = {0,0,0,0}, a1[4] = {0,0,0,0};
            float ks0 = 0.f, ks1 = 0.f;
            #pragma unroll 8
            for (int p = 0; p < 128; p++) {
                float2 k2 = *(const float2*)(Dk + p * DS_STR);
                float4 v4 = *(const float4*)(Vv + p * VS_STR);
                a0[0] += k2.x * v4.x; a0[1] += k2.x * v4.y;
                a0[2] += k2.x * v4.z; a0[3] += k2.x * v4.w;
                a1[0] += k2.y * v4.x; a1[1] += k2.y * v4.y;
                a1[2] += k2.y * v4.z; a1[3] += k2.y * v4.w;
                if (doKs) { ks0 += k2.x; ks1 += k2.y; }
            }
            float* kvdst = g_kv + (((long)(b * 4 + head) * 32 + d0) * 32 + e0);
            #pragma unroll
            for (int j = 0; j < 4; j++) {
                atomicAdd(kvdst + j, a0[j]);
                atomicAdd(kvdst + 32 + j, a1[j]);
            }
            if (doKs) {
                atomicAdd(g_ksum + (b * 4 + head) * 32 + d0,     ks0);
                atomicAdd(g_ksum + (b * 4 + head) * 32 + d0 + 1, ks1);
            }
        }
    }
}

// ---------------------------------------------------------------------------
// att: q read channel-major (lane-coalesced over n).
__global__ __launch_bounds__(256) void att_kernel(float* __restrict__ out) {
    __shared__ float4 kvs4[1024];
    __shared__ float  kms[128];
    int b = blockIdx.y;
    int p0 = blockIdx.x * 128;
    int tid = threadIdx.x;
    const float invHW = 1.f / (float)HW;
    const float4* kvsrc = (const float4*)(g_kv + (long)b * 4096);
    for (int idx = tid; idx < 1024; idx += 256) {
        float4 v = kvsrc[idx];
        v.x *= invHW; v.y *= invHW; v.z *= invHW; v.w *= invHW;
        kvs4[idx] = v;
    }
    if (tid < 128) kms[tid] = g_ksum[b * 128 + tid] * invHW;
    __syncthreads();

    int h = tid >> 6, lp = tid & 63;
    int n1 = p0 + lp, n2 = p0 + 64 + lp;
    bool v1 = n1 < HW, v2 = n2 < HW;
    const float* qb = g_q + ((long)b * GC + h * 32) * HW;

    float q1[32], q2[32];
    #pragma unroll
    for (int d = 0; d < 32; d++) {
        q1[d] = v1 ? qb[(long)d * HW + n1] : 0.f;
        q2[d] = v2 ? qb[(long)d * HW + n2] : 0.f;
    }
    float s1 = 0.f, s2 = 0.f;
    #pragma unroll
    for (int d = 0; d < 32; d++) {
        float km = kms[h * 32 + d];
        s1 += q1[d] * km;
        s2 += q2[d] * km;
    }
    float z1 = 1.f / (s1 + 1e-6f);
    float z2 = 1.f / (s2 + 1e-6f);

    float* ob = out + FEATS_BASE + ((long)b * 384 + h * 32) * HW;
    #pragma unroll
    for (int e4 = 0; e4 < 8; e4++) {
        float4 a1 = make_float4(0,0,0,0), a2 = make_float4(0,0,0,0);
        #pragma unroll
        for (int d = 0; d < 32; d++) {
            float4 kv = kvs4[(h * 32 + d) * 8 + e4];
            a1.x += q1[d] * kv.x; a1.y += q1[d] * kv.y;
            a1.z += q1[d] * kv.z; a1.w += q1[d] * kv.w;
            a2.x += q2[d] * kv.x; a2.y += q2[d] * kv.y;
            a2.z += q2[d] * kv.z; a2.w += q2[d] * kv.w;
        }
        int e = e4 * 4;
        if (v1) {
            ob[(long)(e+0) * HW + n1] = a1.x * z1;
            ob[(long)(e+1) * HW + n1] = a1.y * z1;
            ob[(long)(e+2) * HW + n1] = a1.z * z1;
            ob[(long)(e+3) * HW + n1] = a1.w * z1;
        }
        if (v2) {
            ob[(long)(e+0) * HW + n2] = a2.x * z2;
            ob[(long)(e+1) * HW + n2] = a2.y * z2;
            ob[(long)(e+2) * HW + n2] = a2.z * z2;
            ob[(long)(e+3) * HW + n2] = a2.w * z2;
        }
    }
}

// ---------------------------------------------------------------------------
__global__ __launch_bounds__(112) void dw3_kernel(const float* __restrict__ x,
                                                  const float* __restrict__ w,
                                                  const float* __restrict__ bias,
                                                  float* __restrict__ out) {
    __shared__ float tile[10][60];
    __shared__ float ws[9];
    int y0 = blockIdx.x * 8;
    int c = blockIdx.y, b = blockIdx.z;
    int tid = threadIdx.x;
    const float* in = x + ((long)b * CT + 2 * GC + c) * HW;

    if (tid < 9) ws[tid] = w[c * 9 + tid];
    for (int idx = tid; idx < 10 * 58; idx += 112) {
        int r = idx / 58, cc = idx % 58;
        int iy = y0 - 1 + r, ix = cc - 1;
        tile[r][cc] = (iy >= 0 && iy < H_ && ix >= 0 && ix < W_) ? in[iy * W_ + ix] : 0.f;
    }
    __syncthreads();

    int gx = tid % 14, gy = tid / 14;
    int xb = gx * 4;
    float bb = bias[c];
    float a0 = bb, a1 = bb, a2 = bb, a3 = bb;
    #pragma unroll
    for (int ky = 0; ky < 3; ky++) {
        const float* row = &tile[gy + ky][xb];
        float r[6];
        #pragma unroll
        for (int i = 0; i < 6; i++) r[i] = row[i];
        #pragma unroll
        for (int kx = 0; kx < 3; kx++) {
            float wv = ws[ky * 3 + kx];
            a0 += wv * r[kx + 0];
            a1 += wv * r[kx + 1];
            a2 += wv * r[kx + 2];
            a3 += wv * r[kx + 3];
        }
    }
    float* ob = out + FEATS_BASE + ((long)b * 384 + GC + c) * HW + (y0 + gy) * W_ + xb;
    ob[0] = a0; ob[1] = a1; ob[2] = a2; ob[3] = a3;
}

// ---------------------------------------------------------------------------
__global__ __launch_bounds__(112) void dw7_kernel(const float* __restrict__ x,
                                                  const float* __restrict__ w,
                                                  const float* __restrict__ bias,
                                                  float* __restrict__ out) {
    __shared__ float tile[14][64];
    __shared__ float ws[49];
    int y0 = blockIdx.x * 8;
    int c = blockIdx.y, b = blockIdx.z;
    int tid = threadIdx.x;
    const float* in = x + ((long)b * CT + 3 * GC + c) * HW;

    if (tid < 49) ws[tid] = w[c * 49 + tid];
    for (int idx = tid; idx < 14 * 62; idx += 112) {
        int r = idx / 62, cc = idx % 62;
        int iy = y0 - 3 + r, ix = cc - 3;
        tile[r][cc] = (iy >= 0 && iy < H_ && ix >= 0 && ix < W_) ? in[iy * W_ + ix] : 0.f;
    }
    __syncthreads();

    int gx = tid % 14, gy = tid / 14;
    int xb = gx * 4;
    float bb = bias[c];
    float a0 = bb, a1 = bb, a2 = bb, a3 = bb;
    #pragma unroll
    for (int ky = 0; ky < 7; ky++) {
        const float* row = &tile[gy + ky][xb];
        float r[10];
        #pragma unroll
        for (int i = 0; i < 10; i++) r[i] = row[i];
        #pragma unroll
        for (int kx = 0; kx < 7; kx++) {
            float wv = ws[ky * 7 + kx];
            a0 += wv * r[kx + 0];
            a1 += wv * r[kx + 1];
            a2 += wv * r[kx + 2];
            a3 += wv * r[kx + 3];
        }
    }
    float* ob = out + FEATS_BASE + ((long)b * 384 + 2 * GC + c) * HW + (y0 + gy) * W_ + xb;
    ob[0] = a0; ob[1] = a1; ob[2] = a2; ob[3] = a3;
}

// ---------------------------------------------------------------------------
extern "C" void kernel_launch(void* const* d_in, const int* in_sizes, int n_in,
                              void* d_out, int out_size) {
    const float* x     = (const float*)d_in[0];
    const float* w_dw1 = (const float*)d_in[1];
    const float* b_dw1 = (const float*)d_in[2];
    const float* w_dw2 = (const float*)d_in[3];
    const float* b_dw2 = (const float*)d_in[4];
    const float* w_qk  = (const float*)d_in[5];
    const float* b_qk  = (const float*)d_in[6];
    float* out = (float*)d_out;

    cudaFuncSetAttribute(qk_mma_kernel, cudaFuncAttributeMaxDynamicSharedMemorySize, SM_TOTAL);

    // Three concurrent chains via events (graph-capture fork/join):
    //   s0 (default): prep -> cvt -> q_mma -> (wait k) -> att -> (wait dw)
    //   s1:           copy_mem, dw3, dw7
    //   s2:           (wait cvt) k_mma (fused kv/ksum)
    cudaStream_t s1, s2;
    cudaStreamCreate(&s1);
    cudaStreamCreate(&s2);
    cudaEvent_t eFork, eCvt, eK, eDw;
    cudaEventCreateWithFlags(&eFork, cudaEventDisableTiming);
    cudaEventCreateWithFlags(&eCvt,  cudaEventDisableTiming);
    cudaEventCreateWithFlags(&eK,    cudaEventDisableTiming);
    cudaEventCreateWithFlags(&eDw,   cudaEventDisableTiming);

    cudaEventRecord(eFork, 0);
    cudaStreamWaitEvent(s1, eFork, 0);

    // s1: independent output branch
    copy_mem_kernel<<<(B_ * GC * HW / 4 + 255) / 256, 256, 0, s1>>>((const float4*)x, (float4*)out);
    dw3_kernel<<<dim3(7, GC, B_), 112, 0, s1>>>(x, w_dw1, b_dw1, out);
    dw7_kernel<<<dim3(7, GC, B_), 112, 0, s1>>>(x, w_dw2, b_dw2, out);
    cudaEventRecord(eDw, s1);

    // s0: attention prep chain
    prep_kernel<<<512, 256>>>(w_qk);
    cvt_kernel<<<dim3(98, 4, B_), 256>>>(x);
    cudaEventRecord(eCvt, 0);

    // s2: k GEMM + fused kv/ksum (independent of q GEMM)
    cudaStreamWaitEvent(s2, eCvt, 0);
    qk_mma_kernel<<<dim3(25, 1, B_), 256, SM_TOTAL, s2>>>(x, b_qk, 1);
    cudaEventRecord(eK, s2);

    // s0: q GEMM, then att after k completes
    qk_mma_kernel<<<dim3(25, 1, B_), 256, SM_TOTAL>>>(x, b_qk, 0);
    cudaStreamWaitEvent(0, eK, 0);
    att_kernel<<<dim3(25, B_), 256>>>(out);

    cudaStreamWaitEvent(0, eDw, 0);

    cudaEventDestroy(eFork);
    cudaEventDestroy(eCvt);
    cudaEventDestroy(eK);
    cudaEventDestroy(eDw);
    cudaStreamDestroy(s1);
    cudaStreamDestroy(s2);
}